// round 2
// baseline (speedup 1.0000x reference)
#include <cuda_runtime.h>

// AdditiveAttention: B=4, Q=512, K=512, H=256, E=256, DV=256
//   q = queries @ W_q^T            [B,Q,H]
//   k = keys    @ W_k^T            [B,K,H]
//   s[b,q,k] = sum_h w_v[h] * tanh(q[b,q,h] + k[b,k,h])
//   attn = softmax_k(s);  out = attn @ values   [B,Q,DV]

#define BB 4
#define QQ 512
#define KK 512
#define HH 256
#define EE 256
#define DVV 256

// scratch (device globals: no allocations allowed)
__device__ float4 g_qv[BB * QQ * HH / 4];   // 2 MB
__device__ float4 g_kv[BB * KK * HH / 4];   // 2 MB
__device__ float4 g_sv[BB * QQ * KK / 4];   // 4 MB

__device__ __forceinline__ float tanh_fast(float x) {
    float y;
    asm("tanh.approx.f32 %0, %1;" : "=f"(y) : "f"(x));
    return y;
}

// ---------------------------------------------------------------------------
// Projection GEMM: C[r][h] = sum_e A[r][e] * W[h][e]
// A: [2048, 256] row-major, W: [256, 256] row-major ([out,in]).
// 32x64 tile per block (512 blocks -> ~3.5/SM), 256 threads,
// 2x4 register tile per thread, e-chunk 32.
// blockIdx.z selects (queries,W_q)->g_qv or (keys,W_k)->g_kv.
// ---------------------------------------------------------------------------
__global__ __launch_bounds__(256) void proj_kernel(
    const float* __restrict__ Aq, const float* __restrict__ Wq,
    const float* __restrict__ Ak, const float* __restrict__ Wk)
{
    const float* A; const float* W; float* C;
    if (blockIdx.z == 0) { A = Aq; W = Wq; C = (float*)g_qv; }
    else                 { A = Ak; W = Wk; C = (float*)g_kv; }

    const int row0 = blockIdx.x * 32;   // 0..63 -> rows
    const int col0 = blockIdx.y * 64;   // 0..3  -> h cols

    __shared__ __align__(16) float As[32][34];   // [e][r], padded (even stride)
    __shared__ __align__(16) float Ws[32][68];   // [e][c], padded (16B-aligned rows)

    const int tid = threadIdx.x;
    const int tx = tid & 15;    // -> 4 cols
    const int ty = tid >> 4;    // -> 2 rows

    float c[2][4];
#pragma unroll
    for (int i = 0; i < 2; ++i)
#pragma unroll
        for (int j = 0; j < 4; ++j) c[i][j] = 0.0f;

    const int lr = tid >> 3;     // loader row 0..31
    const int le = tid & 7;      // loader e-quad 0..7 (32 e)

    for (int e0 = 0; e0 < EE; e0 += 32) {
        __syncthreads();
        {
            // A tile: 32 rows x 32 e = 256 float4, 1 per thread
            float4 va = *(const float4*)(A + (size_t)(row0 + lr) * EE + e0 + 4 * le);
            As[4 * le + 0][lr] = va.x;
            As[4 * le + 1][lr] = va.y;
            As[4 * le + 2][lr] = va.z;
            As[4 * le + 3][lr] = va.w;
            // W tile: 64 rows x 32 e = 512 float4, 2 per thread
#pragma unroll
            for (int i = 0; i < 2; ++i) {
                int idx = tid + i * 256;
                int wr = idx >> 3;         // 0..63
                int we = idx & 7;
                float4 vw = *(const float4*)(W + (size_t)(col0 + wr) * EE + e0 + 4 * we);
                Ws[4 * we + 0][wr] = vw.x;
                Ws[4 * we + 1][wr] = vw.y;
                Ws[4 * we + 2][wr] = vw.z;
                Ws[4 * we + 3][wr] = vw.w;
            }
        }
        __syncthreads();
#pragma unroll
        for (int e = 0; e < 32; ++e) {
            float2 a2 = *(const float2*)(&As[e][2 * ty]);
            float4 w4 = *(const float4*)(&Ws[e][4 * tx]);
            c[0][0] = fmaf(a2.x, w4.x, c[0][0]);
            c[0][1] = fmaf(a2.x, w4.y, c[0][1]);
            c[0][2] = fmaf(a2.x, w4.z, c[0][2]);
            c[0][3] = fmaf(a2.x, w4.w, c[0][3]);
            c[1][0] = fmaf(a2.y, w4.x, c[1][0]);
            c[1][1] = fmaf(a2.y, w4.y, c[1][1]);
            c[1][2] = fmaf(a2.y, w4.z, c[1][2]);
            c[1][3] = fmaf(a2.y, w4.w, c[1][3]);
        }
    }

#pragma unroll
    for (int i = 0; i < 2; ++i) {
        float4 o = make_float4(c[i][0], c[i][1], c[i][2], c[i][3]);
        *(float4*)(C + (size_t)(row0 + 2 * ty + i) * HH + col0 + 4 * tx) = o;
    }
}

// ---------------------------------------------------------------------------
// Scores kernel: s[b,q,k] = sum_h w_v[h]*tanh(qp[b,q,h] + kp[b,k,h])
// Grid: 1024 blocks = b(4) x qtile(64, 8 queries) x ksplit(4, 128 keys).
// Block: 256 threads = 8 warps; warp w owns query qt*8+w.
// Lane mapping: lane = kl*8 + hg. Thread owns key kl (of 4 concurrent keys)
// and h subset {4*hg + 32*j : j=0..7} (q/w_v in 64 registers).
// k tile (32 keys x 256 h) in smem, key-major: each LDS.128 phase (8 lanes,
// one key) reads 128 contiguous bytes -> conflict-free.
// Reduction: 3 shfl over 8 lanes, amortized over 4 keys (1 shfl/key vs 5 before).
// MUFU.TANH is the designed bottleneck.
// ---------------------------------------------------------------------------
__global__ __launch_bounds__(256, 2) void scores_kernel(const float* __restrict__ w_v)
{
    __shared__ __align__(16) float kt[32 * HH];   // 32 KB

    const int tid  = threadIdx.x;
    const int w    = tid >> 5;
    const int lane = tid & 31;
    const int kl   = lane >> 3;   // 0..3  key within group
    const int hg   = lane & 7;    // 0..7  h subgroup

    const int bx = blockIdx.x;
    const int b  = bx >> 8;
    const int qt = (bx >> 2) & 63;
    const int ks = bx & 3;
    const int qi = qt * 8 + w;

    const float* gq = (const float*)g_qv;
    const float* gk = (const float*)g_kv;
    float*       gs = (float*)g_sv;

    // q and w_v registers: float4 index hg + 8*j  (h = 4*hg + 32*j)
    const float4* qrow = (const float4*)(gq + (size_t)(b * QQ + qi) * HH);
    const float4* wv4  = (const float4*)w_v;
    float4 qr[8], wr[8];
#pragma unroll
    for (int j = 0; j < 8; ++j) {
        qr[j] = qrow[hg + 8 * j];
        wr[j] = wv4[hg + 8 * j];
    }

    for (int t = 0; t < 4; ++t) {
        const int kbase = ks * 128 + t * 32;
        __syncthreads();
        {
            const float4* ksrc = (const float4*)(gk + (size_t)(b * KK + kbase) * HH);
            float4* kdst = (float4*)kt;
#pragma unroll
            for (int j = 0; j < 8; ++j)
                kdst[tid + j * 256] = ksrc[tid + j * 256];
        }
        __syncthreads();

        float* srow = gs + (size_t)(b * QQ + qi) * KK + kbase;

#pragma unroll 2
        for (int g = 0; g < 8; ++g) {
            const int key = g * 4 + kl;
            const float4* krow = (const float4*)(kt + key * HH);

            float a0 = 0.0f, a1 = 0.0f;
#pragma unroll
            for (int j = 0; j < 8; ++j) {
                const float4 k4 = krow[hg + 8 * j];
                a0 = fmaf(wr[j].x, tanh_fast(qr[j].x + k4.x), a0);
                a1 = fmaf(wr[j].y, tanh_fast(qr[j].y + k4.y), a1);
                a0 = fmaf(wr[j].z, tanh_fast(qr[j].z + k4.z), a0);
                a1 = fmaf(wr[j].w, tanh_fast(qr[j].w + k4.w), a1);
            }
            float acc = a0 + a1;

            // reduce over the 8 hg-lanes of each key
            acc += __shfl_xor_sync(0xffffffffu, acc, 1);
            acc += __shfl_xor_sync(0xffffffffu, acc, 2);
            acc += __shfl_xor_sync(0xffffffffu, acc, 4);
            // gather the 4 key results (lanes 0,8,16,24) to lanes 0..3
            float v = __shfl_sync(0xffffffffu, acc, (lane & 3) * 8);
            if (lane < 4) srow[g * 4 + lane] = v;
        }
    }
}

// ---------------------------------------------------------------------------
// Softmax over K + attn @ V.
// Grid: 128 blocks = b(4) x qtile(32, 16 queries). Block: 512 threads.
// Phase 1: warp w softmaxes score row w (512 values) in smem.
// Phase 2: thread (qp = tid>>6, dq = tid&63) accumulates out[2 queries][4 dv];
//          V row loads are coalesced LDG.128, L1-reused across 16 queries.
// ---------------------------------------------------------------------------
__global__ __launch_bounds__(512) void softmax_av_kernel(
    const float* __restrict__ values, float* __restrict__ out)
{
    __shared__ __align__(16) float p[16 * 512];   // 32 KB
    __shared__ float invs[16];

    const int bx = blockIdx.x;
    const int b  = bx >> 5;
    const int qt = bx & 31;
    const int tid = threadIdx.x;

    {
        const float4* src = (const float4*)((const float*)g_sv + (size_t)(b * QQ + qt * 16) * KK);
        float4* dst = (float4*)p;
#pragma unroll
        for (int j = 0; j < 4; ++j)
            dst[tid + j * 512] = src[tid + j * 512];
    }
    __syncthreads();

    {
        const int w = tid >> 5, lane = tid & 31;
        float* row = p + w * 512;
        float m = -1e30f;
#pragma unroll
        for (int j = 0; j < 16; ++j) m = fmaxf(m, row[lane + 32 * j]);
#pragma unroll
        for (int o = 16; o > 0; o >>= 1)
            m = fmaxf(m, __shfl_xor_sync(0xffffffffu, m, o));
        float sum = 0.0f;
#pragma unroll
        for (int j = 0; j < 16; ++j) {
            float e = __expf(row[lane + 32 * j] - m);
            row[lane + 32 * j] = e;
            sum += e;
        }
#pragma unroll
        for (int o = 16; o > 0; o >>= 1)
            sum += __shfl_xor_sync(0xffffffffu, sum, o);
        if (lane == 0) invs[w] = 1.0f / sum;
    }
    __syncthreads();

    const int dq = tid & 63;   // float4 column of DV
    const int qp = tid >> 6;   // 0..7 -> queries 2qp, 2qp+1
    const float* p0r = p + (2 * qp) * 512;
    const float* p1r = p + (2 * qp + 1) * 512;
    const float4* V = (const float4*)(values + (size_t)b * KK * DVV);

    float4 acc0 = make_float4(0.f, 0.f, 0.f, 0.f);
    float4 acc1 = make_float4(0.f, 0.f, 0.f, 0.f);

#pragma unroll 4
    for (int k = 0; k < KK; ++k) {
        const float4 v = V[k * (DVV / 4) + dq];
        const float a = p0r[k];
        const float c = p1r[k];
        acc0.x = fmaf(a, v.x, acc0.x);
        acc0.y = fmaf(a, v.y, acc0.y);
        acc0.z = fmaf(a, v.z, acc0.z);
        acc0.w = fmaf(a, v.w, acc0.w);
        acc1.x = fmaf(c, v.x, acc1.x);
        acc1.y = fmaf(c, v.y, acc1.y);
        acc1.z = fmaf(c, v.z, acc1.z);
        acc1.w = fmaf(c, v.w, acc1.w);
    }

    const float i0 = invs[2 * qp];
    const float i1 = invs[2 * qp + 1];
    acc0.x *= i0; acc0.y *= i0; acc0.z *= i0; acc0.w *= i0;
    acc1.x *= i1; acc1.y *= i1; acc1.z *= i1; acc1.w *= i1;

    const int q0 = qt * 16 + 2 * qp;
    *(float4*)(out + (size_t)(b * QQ + q0) * DVV + 4 * dq)       = acc0;
    *(float4*)(out + (size_t)(b * QQ + q0 + 1) * DVV + 4 * dq)   = acc1;
}

// ---------------------------------------------------------------------------
extern "C" void kernel_launch(void* const* d_in, const int* in_sizes, int n_in,
                              void* d_out, int out_size)
{
    const float* queries = (const float*)d_in[0];
    const float* keys    = (const float*)d_in[1];
    const float* values  = (const float*)d_in[2];
    const float* W_q     = (const float*)d_in[3];
    const float* W_k     = (const float*)d_in[4];
    const float* w_v     = (const float*)d_in[5];
    float* out = (float*)d_out;

    proj_kernel<<<dim3(64, 4, 2), 256>>>(queries, W_q, keys, W_k);
    scores_kernel<<<1024, 256>>>(w_v);
    softmax_av_kernel<<<128, 512>>>(values, out);
}

// round 3
// speedup vs baseline: 1.1043x; 1.1043x over previous
#include <cuda_runtime.h>
#include <cuda_fp16.h>

// AdditiveAttention: B=4, Q=512, K=512, H=256, E=256, DV=256
//   q = queries @ W_q^T            [B,Q,H]
//   k = keys    @ W_k^T            [B,K,H]
//   s[b,q,k] = sum_h w_v[h] * tanh(q[b,q,h] + k[b,k,h])
//   attn = softmax_k(s);  out = attn @ values   [B,Q,DV]

#define BB 4
#define QQ 512
#define KK 512
#define HH 256
#define EE 256
#define DVV 256

// scratch (device globals: no allocations allowed)
__device__ float4 g_qv[BB * QQ * HH / 4];   // 2 MB
__device__ float4 g_kv[BB * KK * HH / 4];   // 2 MB
__device__ float4 g_sv[BB * QQ * KK / 4];   // 4 MB

__device__ __forceinline__ __half2 tanh2(__half2 x) {
    unsigned xi = *(unsigned*)&x, yi;
    asm("tanh.approx.f16x2 %0, %1;" : "=r"(yi) : "r"(xi));
    return *(__half2*)&yi;
}

// ---------------------------------------------------------------------------
// Projection GEMM: C[r][h] = sum_e A[r][e] * W[h][e]
// A: [2048, 256] row-major, W: [256, 256] row-major ([out,in]).
// 64x64 tile per block, 256 threads, 4x4 register tile, e-chunk 32.
// blockIdx.z selects (queries,W_q)->g_qv or (keys,W_k)->g_kv.
// ---------------------------------------------------------------------------
__global__ __launch_bounds__(256) void proj_kernel(
    const float* __restrict__ Aq, const float* __restrict__ Wq,
    const float* __restrict__ Ak, const float* __restrict__ Wk)
{
    const float* A; const float* W; float* C;
    if (blockIdx.z == 0) { A = Aq; W = Wq; C = (float*)g_qv; }
    else                 { A = Ak; W = Wk; C = (float*)g_kv; }

    const int row0 = blockIdx.x * 64;   // 0..31 -> rows
    const int col0 = blockIdx.y * 64;   // 0..3  -> h cols

    __shared__ __align__(16) float As[32][68];   // [e][r], padded
    __shared__ __align__(16) float Ws[32][68];   // [e][c], padded

    const int tid = threadIdx.x;
    const int tx = tid & 15;
    const int ty = tid >> 4;

    float c[4][4];
#pragma unroll
    for (int i = 0; i < 4; ++i)
#pragma unroll
        for (int j = 0; j < 4; ++j) c[i][j] = 0.0f;

    for (int e0 = 0; e0 < EE; e0 += 32) {
        __syncthreads();
#pragma unroll
        for (int i = 0; i < 2; ++i) {
            const int idx = tid + i * 256;
            const int r  = idx >> 3;    // 0..63
            const int e8 = idx & 7;     // 0..7
            float4 va = *(const float4*)(A + (size_t)(row0 + r) * EE + e0 + 4 * e8);
            As[4 * e8 + 0][r] = va.x;
            As[4 * e8 + 1][r] = va.y;
            As[4 * e8 + 2][r] = va.z;
            As[4 * e8 + 3][r] = va.w;
            float4 vw = *(const float4*)(W + (size_t)(col0 + r) * EE + e0 + 4 * e8);
            Ws[4 * e8 + 0][r] = vw.x;
            Ws[4 * e8 + 1][r] = vw.y;
            Ws[4 * e8 + 2][r] = vw.z;
            Ws[4 * e8 + 3][r] = vw.w;
        }
        __syncthreads();
#pragma unroll
        for (int e = 0; e < 32; ++e) {
            float4 a4 = *(const float4*)(&As[e][4 * ty]);
            float4 w4 = *(const float4*)(&Ws[e][4 * tx]);
            float av[4] = {a4.x, a4.y, a4.z, a4.w};
            float wv[4] = {w4.x, w4.y, w4.z, w4.w};
#pragma unroll
            for (int i = 0; i < 4; ++i)
#pragma unroll
                for (int j = 0; j < 4; ++j)
                    c[i][j] = fmaf(av[i], wv[j], c[i][j]);
        }
    }

#pragma unroll
    for (int i = 0; i < 4; ++i) {
        float4 o = make_float4(c[i][0], c[i][1], c[i][2], c[i][3]);
        *(float4*)(C + (size_t)(row0 + 4 * ty + i) * HH + col0 + 4 * tx) = o;
    }
}

// ---------------------------------------------------------------------------
// Scores kernel (f16x2): s[b,q,k] = sum_h w_v[h]*tanh(q[b,q,h] + k[b,k,h])
// Grid: 1024 blocks = b(4) x qtile(64, 8 queries) x ksplit(4, 128 keys).
// Block: 256 threads = 8 warps; warp w owns query qt*8+w.
// Lane = kl*8+hg: thread owns key kl of 4 concurrent keys, and h pairs
// p = 4*hg + 32*m + c (m=0..3, c=0..3) -> 32 h values as 16 __half2 regs.
// K tile staged as f16x2 [32 keys][128 pairs] (16 KB). LDS.128 at pair
// offset (hg + 8m): each 8-lane phase covers 8 distinct 16B bank groups ->
// conflict-free. Per 2 tanh: 1 HADD2 + 1 MUFU.TANH.f16x2 + 1 HFMA2.
// MUFU op count is half of the f32 version; MUFU remains the bottleneck.
// ---------------------------------------------------------------------------
__global__ __launch_bounds__(256) void scores_kernel(const float* __restrict__ w_v)
{
    __shared__ __align__(16) __half2 kt[32 * 128];   // 16 KB

    const int tid  = threadIdx.x;
    const int w    = tid >> 5;
    const int lane = tid & 31;
    const int kl   = lane >> 3;   // 0..3  key within group
    const int hg   = lane & 7;    // 0..7  h subgroup

    const int bx = blockIdx.x;
    const int b  = bx >> 8;
    const int qt = (bx >> 2) & 63;
    const int ks = bx & 3;
    const int qi = qt * 8 + w;

    const float* gq = (const float*)g_qv;
    const float* gk = (const float*)g_kv;
    float*       gs = (float*)g_sv;

    // Pack q and w_v into f16x2 registers.
    // qp[m][c] covers h = 8*hg + 64*m + 2*c .. +1   (pair p = 4*hg+32*m+c)
    const float4* qrow = (const float4*)(gq + (size_t)(b * QQ + qi) * HH);
    const float4* wv4  = (const float4*)w_v;
    __half2 qp[4][4], wp[4][4];
#pragma unroll
    for (int m = 0; m < 4; ++m) {
        float4 qa = qrow[2 * hg + 16 * m];
        float4 qb = qrow[2 * hg + 16 * m + 1];
        qp[m][0] = __floats2half2_rn(qa.x, qa.y);
        qp[m][1] = __floats2half2_rn(qa.z, qa.w);
        qp[m][2] = __floats2half2_rn(qb.x, qb.y);
        qp[m][3] = __floats2half2_rn(qb.z, qb.w);
        float4 wa = wv4[2 * hg + 16 * m];
        float4 wb = wv4[2 * hg + 16 * m + 1];
        wp[m][0] = __floats2half2_rn(wa.x, wa.y);
        wp[m][1] = __floats2half2_rn(wa.z, wa.w);
        wp[m][2] = __floats2half2_rn(wb.x, wb.y);
        wp[m][3] = __floats2half2_rn(wb.z, wb.w);
    }

    for (int t = 0; t < 4; ++t) {
        const int kbase = ks * 128 + t * 32;
        __syncthreads();
        {
            // stage 32 keys x 256 h, converting f32 -> f16x2
            const float4* ksrc = (const float4*)(gk + (size_t)(b * KK + kbase) * HH);
#pragma unroll
            for (int j = 0; j < 8; ++j) {
                const int idx = tid + j * 256;          // float4 index
                const int key = idx >> 6;               // 0..31
                const int i4  = idx & 63;               // float4 within key
                float4 v = ksrc[idx];
                __half2* dst = kt + key * 128 + 2 * i4;
                dst[0] = __floats2half2_rn(v.x, v.y);
                dst[1] = __floats2half2_rn(v.z, v.w);
            }
        }
        __syncthreads();

        float* srow = gs + (size_t)(b * QQ + qi) * KK + kbase;

#pragma unroll 2
        for (int g = 0; g < 8; ++g) {
            const int key = g * 4 + kl;
            const uint4* krow = (const uint4*)(kt + key * 128);

            __half2 acc0 = __floats2half2_rn(0.f, 0.f);
            __half2 acc1 = acc0, acc2 = acc0, acc3 = acc0;
#pragma unroll
            for (int m = 0; m < 4; ++m) {
                uint4 kv = krow[hg + 8 * m];
                __half2 k0 = *(__half2*)&kv.x;
                __half2 k1 = *(__half2*)&kv.y;
                __half2 k2 = *(__half2*)&kv.z;
                __half2 k3 = *(__half2*)&kv.w;
                acc0 = __hfma2(wp[m][0], tanh2(__hadd2(qp[m][0], k0)), acc0);
                acc1 = __hfma2(wp[m][1], tanh2(__hadd2(qp[m][1], k1)), acc1);
                acc2 = __hfma2(wp[m][2], tanh2(__hadd2(qp[m][2], k2)), acc2);
                acc3 = __hfma2(wp[m][3], tanh2(__hadd2(qp[m][3], k3)), acc3);
            }
            float2 f0 = __half22float2(acc0);
            float2 f1 = __half22float2(acc1);
            float2 f2 = __half22float2(acc2);
            float2 f3 = __half22float2(acc3);
            float s = ((f0.x + f0.y) + (f1.x + f1.y)) +
                      ((f2.x + f2.y) + (f3.x + f3.y));

            // reduce over the 8 hg-lanes of each key
            s += __shfl_xor_sync(0xffffffffu, s, 1);
            s += __shfl_xor_sync(0xffffffffu, s, 2);
            s += __shfl_xor_sync(0xffffffffu, s, 4);
            // gather the 4 key results (lanes 0,8,16,24) to lanes 0..3
            float v = __shfl_sync(0xffffffffu, s, (lane & 3) * 8);
            if (lane < 4) srow[g * 4 + lane] = v;
        }
    }
}

// ---------------------------------------------------------------------------
// Softmax over K + attn @ V.
// Grid: 128 blocks = b(4) x qtile(32, 16 queries). Block: 512 threads.
// ---------------------------------------------------------------------------
__global__ __launch_bounds__(512) void softmax_av_kernel(
    const float* __restrict__ values, float* __restrict__ out)
{
    __shared__ __align__(16) float p[16 * 512];   // 32 KB
    __shared__ float invs[16];

    const int bx = blockIdx.x;
    const int b  = bx >> 5;
    const int qt = bx & 31;
    const int tid = threadIdx.x;

    {
        const float4* src = (const float4*)((const float*)g_sv + (size_t)(b * QQ + qt * 16) * KK);
        float4* dst = (float4*)p;
#pragma unroll
        for (int j = 0; j < 4; ++j)
            dst[tid + j * 512] = src[tid + j * 512];
    }
    __syncthreads();

    {
        const int w = tid >> 5, lane = tid & 31;
        float* row = p + w * 512;
        float m = -1e30f;
#pragma unroll
        for (int j = 0; j < 16; ++j) m = fmaxf(m, row[lane + 32 * j]);
#pragma unroll
        for (int o = 16; o > 0; o >>= 1)
            m = fmaxf(m, __shfl_xor_sync(0xffffffffu, m, o));
        float sum = 0.0f;
#pragma unroll
        for (int j = 0; j < 16; ++j) {
            float e = __expf(row[lane + 32 * j] - m);
            row[lane + 32 * j] = e;
            sum += e;
        }
#pragma unroll
        for (int o = 16; o > 0; o >>= 1)
            sum += __shfl_xor_sync(0xffffffffu, sum, o);
        if (lane == 0) invs[w] = 1.0f / sum;
    }
    __syncthreads();

    const int dq = tid & 63;   // float4 column of DV
    const int qp = tid >> 6;   // 0..7 -> queries 2qp, 2qp+1
    const float* p0r = p + (2 * qp) * 512;
    const float* p1r = p + (2 * qp + 1) * 512;
    const float4* V = (const float4*)(values + (size_t)b * KK * DVV);

    float4 acc0 = make_float4(0.f, 0.f, 0.f, 0.f);
    float4 acc1 = make_float4(0.f, 0.f, 0.f, 0.f);

#pragma unroll 4
    for (int k = 0; k < KK; ++k) {
        const float4 v = V[k * (DVV / 4) + dq];
        const float a = p0r[k];
        const float c = p1r[k];
        acc0.x = fmaf(a, v.x, acc0.x);
        acc0.y = fmaf(a, v.y, acc0.y);
        acc0.z = fmaf(a, v.z, acc0.z);
        acc0.w = fmaf(a, v.w, acc0.w);
        acc1.x = fmaf(c, v.x, acc1.x);
        acc1.y = fmaf(c, v.y, acc1.y);
        acc1.z = fmaf(c, v.z, acc1.z);
        acc1.w = fmaf(c, v.w, acc1.w);
    }

    const float i0 = invs[2 * qp];
    const float i1 = invs[2 * qp + 1];
    acc0.x *= i0; acc0.y *= i0; acc0.z *= i0; acc0.w *= i0;
    acc1.x *= i1; acc1.y *= i1; acc1.z *= i1; acc1.w *= i1;

    const int q0 = qt * 16 + 2 * qp;
    *(float4*)(out + (size_t)(b * QQ + q0) * DVV + 4 * dq)       = acc0;
    *(float4*)(out + (size_t)(b * QQ + q0 + 1) * DVV + 4 * dq)   = acc1;
}

// ---------------------------------------------------------------------------
extern "C" void kernel_launch(void* const* d_in, const int* in_sizes, int n_in,
                              void* d_out, int out_size)
{
    const float* queries = (const float*)d_in[0];
    const float* keys    = (const float*)d_in[1];
    const float* values  = (const float*)d_in[2];
    const float* W_q     = (const float*)d_in[3];
    const float* W_k     = (const float*)d_in[4];
    const float* w_v     = (const float*)d_in[5];
    float* out = (float*)d_out;

    proj_kernel<<<dim3(32, 4, 2), 256>>>(queries, W_q, keys, W_k);
    scores_kernel<<<1024, 256>>>(w_v);
    softmax_av_kernel<<<128, 512>>>(values, out);
}